// round 1
// baseline (speedup 1.0000x reference)
#include <cuda_runtime.h>
#include <cuda_bf16.h>
#include <cstdint>

#define NN 20000
#define DIN 128
#define HIDC 128
#define NHEADS 4
#define MAXM (NHEADS * HIDC)      // 512
#define EMAX 320000
#define ETOTMAX (EMAX + NN)       // 340000

// -------------------- scratch (device globals; no runtime alloc) -----------
__device__ float    g_xl [NN * MAXM];
__device__ float    g_acc[NN * MAXM];
__device__ float    g_h1 [NN * MAXM];
__device__ float    g_h2 [NN * MAXM];
__device__ float    g_as [NN * NHEADS];
__device__ float    g_ad [NN * NHEADS];
__device__ unsigned g_mkey[NN * NHEADS];
__device__ float    g_den[NN * NHEADS];
__device__ float    g_ex [ETOTMAX * NHEADS];
__device__ float    g_pool[HIDC];

// -------------------- helpers ----------------------------------------------
__device__ __forceinline__ unsigned fkey(float f) {
    unsigned b = __float_as_uint(f);
    return (b & 0x80000000u) ? ~b : (b | 0x80000000u);
}
__device__ __forceinline__ float funkey(unsigned k) {
    unsigned b = (k & 0x80000000u) ? (k & 0x7fffffffu) : ~k;
    return __uint_as_float(b);
}
__device__ __forceinline__ void edge_sd(const int* __restrict__ ei, int E, int e,
                                        int& s, int& d) {
    if (e < E) { s = ei[e]; d = ei[E + e]; }
    else       { s = d = e - E; }               // self loops appended
}

// -------------------- init --------------------------------------------------
__global__ void k_init(float* acc, unsigned* mkey, float* den, float* pool,
                       int nm, int nh) {
    int i = blockIdx.x * blockDim.x + threadIdx.x;
    if (i < nm) acc[i] = 0.f;
    if (i < nh) { mkey[i] = 0u; den[i] = 0.f; }
    if (i < HIDC) pool[i] = 0.f;
}

// -------------------- GEMM: C[n,M] = A[n,K] @ B[K,M] ------------------------
// 64x64 tile, BK=16, 256 threads, 4x4 per thread. K%16==0, M%64==0 assumed.
__global__ void k_gemm(const float* __restrict__ A, const float* __restrict__ B,
                       float* __restrict__ C, int n, int K, int M) {
    __shared__ float As[16][68];
    __shared__ float Bs[16][68];
    int tid = threadIdx.x;
    int row0 = blockIdx.y * 64, col0 = blockIdx.x * 64;
    int tx = tid & 15, ty = tid >> 4;
    int a_r = tid >> 2, a_c = (tid & 3) * 4;
    int b_r = tid >> 4, b_c = (tid & 15) * 4;
    float acc[4][4] = {};
    for (int kt = 0; kt < K; kt += 16) {
        float4 av = make_float4(0.f, 0.f, 0.f, 0.f);
        int ar = row0 + a_r;
        if (ar < n) av = *(const float4*)(A + (size_t)ar * K + kt + a_c);
        As[a_c + 0][a_r] = av.x; As[a_c + 1][a_r] = av.y;
        As[a_c + 2][a_r] = av.z; As[a_c + 3][a_r] = av.w;
        float4 bv = *(const float4*)(B + (size_t)(kt + b_r) * M + col0 + b_c);
        *(float4*)&Bs[b_r][b_c] = bv;
        __syncthreads();
#pragma unroll
        for (int k = 0; k < 16; k++) {
            float ra[4], rb[4];
#pragma unroll
            for (int i = 0; i < 4; i++) ra[i] = As[k][ty * 4 + i];
#pragma unroll
            for (int j = 0; j < 4; j++) rb[j] = Bs[k][tx * 4 + j];
#pragma unroll
            for (int i = 0; i < 4; i++)
#pragma unroll
                for (int j = 0; j < 4; j++) acc[i][j] += ra[i] * rb[j];
        }
        __syncthreads();
    }
#pragma unroll
    for (int i = 0; i < 4; i++) {
        int r = row0 + ty * 4 + i;
        if (r < n) {
            float4 v = make_float4(acc[i][0], acc[i][1], acc[i][2], acc[i][3]);
            *(float4*)(C + (size_t)r * M + col0 + tx * 4) = v;
        }
    }
}

// -------------------- attention scores per node/head ------------------------
// grid = n, block = 32*H. warp h: dot(xl[n, h*C : h*C+C], a_s[h]) etc.
__global__ void k_attn(const float* __restrict__ xl, const float* __restrict__ a_s,
                       const float* __restrict__ a_d, float* __restrict__ outs,
                       float* __restrict__ outd, int H, int C, int M) {
    int n = blockIdx.x;
    int w = threadIdx.x >> 5, lane = threadIdx.x & 31;
    const float* row = xl + (size_t)n * M + w * C;
    float ss = 0.f, sd = 0.f;
    for (int c = lane; c < C; c += 32) {
        float v = row[c];
        ss += v * a_s[w * C + c];
        sd += v * a_d[w * C + c];
    }
#pragma unroll
    for (int o = 16; o; o >>= 1) {
        ss += __shfl_xor_sync(0xffffffffu, ss, o);
        sd += __shfl_xor_sync(0xffffffffu, sd, o);
    }
    if (lane == 0) { outs[n * H + w] = ss; outd[n * H + w] = sd; }
}

// -------------------- segment max over dst ----------------------------------
__global__ void k_edge_max(const int* __restrict__ ei, int E, int Etot,
                           const float* __restrict__ as, const float* __restrict__ ad,
                           unsigned* __restrict__ mkey, int H) {
    int e = blockIdx.x * blockDim.x + threadIdx.x;
    if (e >= Etot) return;
    int s, d; edge_sd(ei, E, e, s, d);
    for (int h = 0; h < H; h++) {
        float v = as[s * H + h] + ad[d * H + h];
        v = v > 0.f ? v : 0.2f * v;                 // leaky_relu(0.2)
        atomicMax(&mkey[d * H + h], fkey(v));
    }
}

// -------------------- exp & segment sum -------------------------------------
__global__ void k_edge_expsum(const int* __restrict__ ei, int E, int Etot,
                              const float* __restrict__ as, const float* __restrict__ ad,
                              const unsigned* __restrict__ mkey,
                              float* __restrict__ den, float* __restrict__ ex, int H) {
    int e = blockIdx.x * blockDim.x + threadIdx.x;
    if (e >= Etot) return;
    int s, d; edge_sd(ei, E, e, s, d);
    for (int h = 0; h < H; h++) {
        float v = as[s * H + h] + ad[d * H + h];
        v = v > 0.f ? v : 0.2f * v;
        float m = funkey(mkey[d * H + h]);
        float x = __expf(v - m);
        ex[e * H + h] = x;
        atomicAdd(&den[d * H + h], x);
    }
}

// -------------------- weighted scatter-add aggregation ----------------------
// one block (C threads) per edge
__global__ void k_edge_agg(const int* __restrict__ ei, int E,
                           const float* __restrict__ xl, const float* __restrict__ ex,
                           const float* __restrict__ den, float* __restrict__ acc,
                           int H, int C, int M) {
    int e = blockIdx.x;
    int s, d; edge_sd(ei, E, e, s, d);
    int t = threadIdx.x;
#pragma unroll 4
    for (int k = 0; k < H; k++) {
        float coef = ex[e * H + k] / den[d * H + k];
        int j = k * C + t;
        atomicAdd(&acc[(size_t)d * M + j], coef * xl[(size_t)s * M + j]);
    }
}

// -------------------- bias (+relu) ------------------------------------------
__global__ void k_finalize(const float* __restrict__ acc, const float* __restrict__ b,
                           float* __restrict__ out, int M, int relu, int total) {
    int i = blockIdx.x * blockDim.x + threadIdx.x;
    if (i >= total) return;
    float v = acc[i] + b[i % M];
    if (relu) v = fmaxf(v, 0.f);
    out[i] = v;
}

// -------------------- mean pool ---------------------------------------------
__global__ void k_pool(const float* __restrict__ h, float* __restrict__ pool, int n) {
    int t = threadIdx.x;  // 128
    float s = 0.f;
    for (int r = blockIdx.x; r < n; r += gridDim.x)
        s += h[(size_t)r * HIDC + t];
    atomicAdd(&pool[t], s);
}

// -------------------- output MLP --------------------------------------------
__global__ void k_mlp(const float* __restrict__ pool, const float* __restrict__ Wm1,
                      const float* __restrict__ bm1, const float* __restrict__ Wm2,
                      const float* __restrict__ bm2, float* __restrict__ out,
                      float invn) {
    __shared__ float g[HIDC];
    __shared__ float t1[HIDC / 2];
    int t = threadIdx.x;  // 128
    g[t] = pool[t] * invn;
    __syncthreads();
    if (t < HIDC / 2) {
        float s = bm1[t];
#pragma unroll 8
        for (int i = 0; i < HIDC; i++) s += g[i] * Wm1[i * (HIDC / 2) + t];
        t1[t] = fmaxf(s, 0.f);
    }
    __syncthreads();
    if (t == 0) {
        float s = bm2[0];
#pragma unroll 8
        for (int j = 0; j < HIDC / 2; j++) s += t1[j] * Wm2[j];
        out[0] = s;
    }
}

// ============================================================================
extern "C" void kernel_launch(void* const* d_in, const int* in_sizes, int n_in,
                              void* d_out, int out_size) {
    const float* x    = (const float*)d_in[0];
    const int*   ei   = (const int*)  d_in[1];   // [2,E] int32 (JAX canonicalizes)
    const float* W0   = (const float*)d_in[2];
    const float* as0  = (const float*)d_in[3];
    const float* ad0  = (const float*)d_in[4];
    const float* b0   = (const float*)d_in[5];
    const float* W1   = (const float*)d_in[6];
    const float* as1  = (const float*)d_in[7];
    const float* ad1  = (const float*)d_in[8];
    const float* b1   = (const float*)d_in[9];
    const float* W2   = (const float*)d_in[10];
    const float* as2  = (const float*)d_in[11];
    const float* ad2  = (const float*)d_in[12];
    const float* b2   = (const float*)d_in[13];
    const float* Wm1  = (const float*)d_in[14];
    const float* bm1  = (const float*)d_in[15];
    const float* Wm2  = (const float*)d_in[16];
    const float* bm2  = (const float*)d_in[17];

    int n = in_sizes[0] / DIN;        // 20000
    int E = in_sizes[1] / 2;          // 320000
    int Etot = E + n;

    float *xl, *acc, *h1, *h2, *as, *ad, *den, *ex, *pool;
    unsigned* mkey;
    { void* p;
      cudaGetSymbolAddress(&p, g_xl);   xl   = (float*)p;
      cudaGetSymbolAddress(&p, g_acc);  acc  = (float*)p;
      cudaGetSymbolAddress(&p, g_h1);   h1   = (float*)p;
      cudaGetSymbolAddress(&p, g_h2);   h2   = (float*)p;
      cudaGetSymbolAddress(&p, g_as);   as   = (float*)p;
      cudaGetSymbolAddress(&p, g_ad);   ad   = (float*)p;
      cudaGetSymbolAddress(&p, g_den);  den  = (float*)p;
      cudaGetSymbolAddress(&p, g_ex);   ex   = (float*)p;
      cudaGetSymbolAddress(&p, g_pool); pool = (float*)p;
      cudaGetSymbolAddress(&p, g_mkey); mkey = (unsigned*)p;
    }

    auto run_layer = [&](const float* in, int K, int H, int C,
                         const float* W, const float* a_s, const float* a_d,
                         const float* b, float* out, int relu) {
        int M = H * C;
        dim3 gg(M / 64, (n + 63) / 64);
        k_gemm<<<gg, 256>>>(in, W, xl, n, K, M);
        int nm = n * M, nh = n * H;
        k_init<<<(nm + 255) / 256, 256>>>(acc, mkey, den, pool, nm, nh);
        k_attn<<<n, 32 * H>>>(xl, a_s, a_d, as, ad, H, C, M);
        k_edge_max   <<<(Etot + 255) / 256, 256>>>(ei, E, Etot, as, ad, mkey, H);
        k_edge_expsum<<<(Etot + 255) / 256, 256>>>(ei, E, Etot, as, ad, mkey, den, ex, H);
        k_edge_agg   <<<Etot, C>>>(ei, E, xl, ex, den, acc, H, C, M);
        k_finalize   <<<(nm + 255) / 256, 256>>>(acc, b, out, M, relu, nm);
    };

    run_layer(x,  DIN,        NHEADS, HIDC, W0, as0, ad0, b0, h1, 1);
    run_layer(h1, NHEADS*HIDC, NHEADS, HIDC, W1, as1, ad1, b1, h2, 1);
    run_layer(h2, NHEADS*HIDC, 1,      HIDC, W2, as2, ad2, b2, h1, 0);

    k_pool<<<256, HIDC>>>(h1, pool, n);
    k_mlp<<<1, HIDC>>>(pool, Wm1, bm1, Wm2, bm2, (float*)d_out, 1.f / (float)n);
}

// round 3
// speedup vs baseline: 2.6854x; 2.6854x over previous
#include <cuda_runtime.h>
#include <cuda_bf16.h>
#include <cstdint>

#define NN 20000
#define DIN 128
#define HIDC 128
#define NHEADS 4
#define MAXM (NHEADS * HIDC)      // 512
#define EMAX 320000
#define ETOTMAX (EMAX + NN)       // 340000

// -------------------- scratch (device globals; no runtime alloc) -----------
__device__ float    g_xl [NN * MAXM];
__device__ float    g_h1 [NN * MAXM];
__device__ float    g_h2 [NN * MAXM];
__device__ float    g_as [NN * NHEADS];
__device__ float    g_ad [NN * NHEADS];
__device__ float    g_pool[HIDC];
__device__ int      g_csr_src[ETOTMAX];
__device__ int      g_row_ptr[NN + 1];
__device__ int      g_cnt[NN];
__device__ int      g_cursor[NN];

// -------------------- helpers ----------------------------------------------
__device__ __forceinline__ uint32_t cvt_tf32(float f) {
    uint32_t o;
    asm volatile("cvt.rna.tf32.f32 %0, %1;" : "=r"(o) : "f"(f));
    return o;
}
__device__ __forceinline__ void edge_sd(const int* __restrict__ ei, int E, int e,
                                        int& s, int& d) {
    if (e < E) { s = ei[e]; d = ei[E + e]; }
    else       { s = d = e - E; }               // self loops appended
}

// ==================== CSR build =============================================
__global__ void k_zero_cnt(int* cnt, int n) {
    int i = blockIdx.x * blockDim.x + threadIdx.x;
    if (i < n) cnt[i] = 0;
}
__global__ void k_count(const int* __restrict__ ei, int E, int Etot,
                        int* __restrict__ cnt) {
    int e = blockIdx.x * blockDim.x + threadIdx.x;
    if (e >= Etot) return;
    int s, d; edge_sd(ei, E, e, s, d);
    atomicAdd(&cnt[d], 1);
}
// single block, 1024 threads: exclusive scan of cnt into row_ptr (+cursor copy)
__global__ void k_scan(const int* __restrict__ cnt, int* __restrict__ row_ptr,
                       int* __restrict__ cursor, int n) {
    __shared__ int part[1024];
    int t = threadIdx.x;
    int per = (n + 1023) / 1024;
    int begi = t * per;
    int endi = min(n, begi + per);
    int s = 0;
    for (int i = begi; i < endi; i++) s += cnt[i];
    part[t] = s;
    __syncthreads();
    for (int o = 1; o < 1024; o <<= 1) {
        int v = (t >= o) ? part[t - o] : 0;
        __syncthreads();
        part[t] += v;
        __syncthreads();
    }
    int off = t ? part[t - 1] : 0;
    for (int i = begi; i < endi; i++) {
        row_ptr[i] = off; cursor[i] = off;
        off += cnt[i];
    }
    if (t == 1023) row_ptr[n] = part[1023];
}
__global__ void k_scatter(const int* __restrict__ ei, int E, int Etot,
                          int* __restrict__ cursor, int* __restrict__ csr_src) {
    int e = blockIdx.x * blockDim.x + threadIdx.x;
    if (e >= Etot) return;
    int s, d; edge_sd(ei, E, e, s, d);
    int pos = atomicAdd(&cursor[d], 1);
    csr_src[pos] = s;
}

// ==================== tf32 tensor-core GEMM =================================
// C[n,M] = A[n,K] @ B[K,M].  BM=128, BN=64, BK=32, 256 threads, 8 warps (4x2).
#define BM 128
#define BN 64
#define BK 32

__device__ __forceinline__ void mma_tf32(float* c, const uint32_t* a, const uint32_t* b) {
    asm volatile(
        "mma.sync.aligned.m16n8k8.row.col.f32.tf32.tf32.f32 "
        "{%0,%1,%2,%3}, {%4,%5,%6,%7}, {%8,%9}, {%0,%1,%2,%3};"
        : "+f"(c[0]), "+f"(c[1]), "+f"(c[2]), "+f"(c[3])
        : "r"(a[0]), "r"(a[1]), "r"(a[2]), "r"(a[3]), "r"(b[0]), "r"(b[1]));
}

__global__ __launch_bounds__(256) void k_gemm_tf32(
    const float* __restrict__ A, const float* __restrict__ B,
    float* __restrict__ C, int n, int K, int M) {
    __shared__ uint32_t As[BM][BK + 4];   // [m][k]
    __shared__ uint32_t Bs[BK][BN + 4];   // [k][n]
    int tid = threadIdx.x;
    int warp = tid >> 5, lane = tid & 31;
    int gid = lane >> 2, tig = lane & 3;
    int warpM = warp & 3, warpN = warp >> 2;
    int row0 = blockIdx.y * BM, col0 = blockIdx.x * BN;

    float c[2][4][4] = {};

    int ar = tid >> 3;            // 0..31, +32 per pass (4 passes)
    int ac = (tid & 7) * 4;       // k-col
    int br = tid >> 4;            // 0..15, +16 per pass (2 passes)
    int bc = (tid & 15) * 4;      // n-col

    for (int kt = 0; kt < K; kt += BK) {
#pragma unroll
        for (int p = 0; p < 4; p++) {
            int r = ar + p * 32;
            int grow = row0 + r;
            float4 v = make_float4(0.f, 0.f, 0.f, 0.f);
            if (grow < n) v = *(const float4*)(A + (size_t)grow * K + kt + ac);
            uint4 u;
            u.x = cvt_tf32(v.x); u.y = cvt_tf32(v.y);
            u.z = cvt_tf32(v.z); u.w = cvt_tf32(v.w);
            *(uint4*)&As[r][ac] = u;
        }
#pragma unroll
        for (int p = 0; p < 2; p++) {
            int r = br + p * 16;
            float4 v = *(const float4*)(B + (size_t)(kt + r) * M + col0 + bc);
            uint4 u;
            u.x = cvt_tf32(v.x); u.y = cvt_tf32(v.y);
            u.z = cvt_tf32(v.z); u.w = cvt_tf32(v.w);
            *(uint4*)&Bs[r][bc] = u;
        }
        __syncthreads();
#pragma unroll
        for (int kk = 0; kk < BK; kk += 8) {
            uint32_t afr[2][4];
#pragma unroll
            for (int t = 0; t < 2; t++) {
                int m = warpM * 32 + t * 16 + gid;
                afr[t][0] = As[m][kk + tig];
                afr[t][1] = As[m + 8][kk + tig];
                afr[t][2] = As[m][kk + tig + 4];
                afr[t][3] = As[m + 8][kk + tig + 4];
            }
            uint32_t bfr[4][2];
#pragma unroll
            for (int t = 0; t < 4; t++) {
                int nn2 = warpN * 32 + t * 8 + gid;
                bfr[t][0] = Bs[kk + tig][nn2];
                bfr[t][1] = Bs[kk + tig + 4][nn2];
            }
#pragma unroll
            for (int i = 0; i < 2; i++)
#pragma unroll
                for (int j = 0; j < 4; j++)
                    mma_tf32(c[i][j], afr[i], bfr[j]);
        }
        __syncthreads();
    }
    // store
#pragma unroll
    for (int i = 0; i < 2; i++) {
        int r0 = row0 + warpM * 32 + i * 16 + gid;
#pragma unroll
        for (int j = 0; j < 4; j++) {
            int cc = col0 + warpN * 32 + j * 8 + tig * 2;
            if (r0 < n)
                *(float2*)(C + (size_t)r0 * M + cc) = make_float2(c[i][j][0], c[i][j][1]);
            if (r0 + 8 < n)
                *(float2*)(C + (size_t)(r0 + 8) * M + cc) = make_float2(c[i][j][2], c[i][j][3]);
        }
    }
}

// ==================== attention scores per node/head ========================
__global__ void k_attn(const float* __restrict__ xl, const float* __restrict__ a_s,
                       const float* __restrict__ a_d, float* __restrict__ outs,
                       float* __restrict__ outd, int H, int C, int M) {
    int n = blockIdx.x;
    int w = threadIdx.x >> 5, lane = threadIdx.x & 31;
    const float* row = xl + (size_t)n * M + w * C;
    float ss = 0.f, sd = 0.f;
    for (int c = lane; c < C; c += 32) {
        float v = row[c];
        ss += v * a_s[w * C + c];
        sd += v * a_d[w * C + c];
    }
#pragma unroll
    for (int o = 16; o; o >>= 1) {
        ss += __shfl_xor_sync(0xffffffffu, ss, o);
        sd += __shfl_xor_sync(0xffffffffu, sd, o);
    }
    if (lane == 0) { outs[n * H + w] = ss; outd[n * H + w] = sd; }
}

// ==================== fused softmax + aggregate + bias (+relu) ==============
// one warp per (node, head); C == 128
__global__ void k_node_agg(const int* __restrict__ csr_src,
                           const int* __restrict__ row_ptr,
                           const float* __restrict__ xl,
                           const float* __restrict__ as,
                           const float* __restrict__ ad,
                           const float* __restrict__ b,
                           float* __restrict__ out,
                           int n, int H, int M, int relu) {
    int w = (blockIdx.x * blockDim.x + threadIdx.x) >> 5;
    if (w >= n * H) return;
    int node = w / H, h = w - node * H;
    int lane = threadIdx.x & 31;
    int beg = row_ptr[node], end = row_ptr[node + 1];
    int deg = end - beg;
    float ad_n = ad[node * H + h];

    // pass 1: segment max
    float m = -3.4e38f;
    for (int i = lane; i < deg; i += 32) {
        int s = csr_src[beg + i];
        float e = as[s * H + h] + ad_n;
        e = e > 0.f ? e : 0.2f * e;
        m = fmaxf(m, e);
    }
#pragma unroll
    for (int o = 16; o; o >>= 1) m = fmaxf(m, __shfl_xor_sync(0xffffffffu, m, o));

    // pass 2: exp weights + unnormalized weighted aggregation
    float den = 0.f;
    float acc0 = 0.f, acc1 = 0.f, acc2 = 0.f, acc3 = 0.f;
    for (int i0 = 0; i0 < deg; i0 += 32) {
        int i = i0 + lane;
        float x = 0.f; int s = 0;
        if (i < deg) {
            s = csr_src[beg + i];
            float e = as[s * H + h] + ad_n;
            e = e > 0.f ? e : 0.2f * e;
            x = __expf(e - m);
            den += x;
        }
        int cnt = min(32, deg - i0);
        for (int j = 0; j < cnt; j++) {
            float xj = __shfl_sync(0xffffffffu, x, j);
            int   sj = __shfl_sync(0xffffffffu, s, j);
            const float* row = xl + (size_t)sj * M + h * HIDC;
            acc0 += xj * row[lane];
            acc1 += xj * row[lane + 32];
            acc2 += xj * row[lane + 64];
            acc3 += xj * row[lane + 96];
        }
    }
#pragma unroll
    for (int o = 16; o; o >>= 1) den += __shfl_xor_sync(0xffffffffu, den, o);
    float inv = 1.f / den;

    size_t base = (size_t)node * M + h * HIDC;
    float v0 = acc0 * inv + b[h * HIDC + lane];
    float v1 = acc1 * inv + b[h * HIDC + lane + 32];
    float v2 = acc2 * inv + b[h * HIDC + lane + 64];
    float v3 = acc3 * inv + b[h * HIDC + lane + 96];
    if (relu) {
        v0 = fmaxf(v0, 0.f); v1 = fmaxf(v1, 0.f);
        v2 = fmaxf(v2, 0.f); v3 = fmaxf(v3, 0.f);
    }
    out[base + lane]      = v0;
    out[base + lane + 32] = v1;
    out[base + lane + 64] = v2;
    out[base + lane + 96] = v3;
}

// ==================== pool + MLP ============================================
__global__ void k_zero_pool(float* pool) {
    pool[threadIdx.x] = 0.f;
}
__global__ void k_pool(const float* __restrict__ h, float* __restrict__ pool, int n) {
    int t = threadIdx.x;  // 128
    float s = 0.f;
    for (int r = blockIdx.x; r < n; r += gridDim.x)
        s += h[(size_t)r * HIDC + t];
    atomicAdd(&pool[t], s);
}
__global__ void k_mlp(const float* __restrict__ pool, const float* __restrict__ Wm1,
                      const float* __restrict__ bm1, const float* __restrict__ Wm2,
                      const float* __restrict__ bm2, float* __restrict__ out,
                      float invn) {
    __shared__ float g[HIDC];
    __shared__ float t1[HIDC / 2];
    int t = threadIdx.x;  // 128
    g[t] = pool[t] * invn;
    __syncthreads();
    if (t < HIDC / 2) {
        float s = bm1[t];
#pragma unroll 8
        for (int i = 0; i < HIDC; i++) s += g[i] * Wm1[i * (HIDC / 2) + t];
        t1[t] = fmaxf(s, 0.f);
    }
    __syncthreads();
    if (t == 0) {
        float s = bm2[0];
#pragma unroll 8
        for (int j = 0; j < HIDC / 2; j++) s += t1[j] * Wm2[j];
        out[0] = s;
    }
}

// ============================================================================
extern "C" void kernel_launch(void* const* d_in, const int* in_sizes, int n_in,
                              void* d_out, int out_size) {
    const float* x    = (const float*)d_in[0];
    const int*   ei   = (const int*)  d_in[1];
    const float* W0   = (const float*)d_in[2];
    const float* as0  = (const float*)d_in[3];
    const float* ad0  = (const float*)d_in[4];
    const float* b0   = (const float*)d_in[5];
    const float* W1   = (const float*)d_in[6];
    const float* as1  = (const float*)d_in[7];
    const float* ad1  = (const float*)d_in[8];
    const float* b1   = (const float*)d_in[9];
    const float* W2   = (const float*)d_in[10];
    const float* as2  = (const float*)d_in[11];
    const float* ad2  = (const float*)d_in[12];
    const float* b2   = (const float*)d_in[13];
    const float* Wm1  = (const float*)d_in[14];
    const float* bm1  = (const float*)d_in[15];
    const float* Wm2  = (const float*)d_in[16];
    const float* bm2  = (const float*)d_in[17];

    int n = in_sizes[0] / DIN;        // 20000
    int E = in_sizes[1] / 2;          // 320000
    int Etot = E + n;

    float *xl, *h1, *h2, *as, *ad, *pool;
    int *csr_src, *row_ptr, *cnt, *cursor;
    { void* p;
      cudaGetSymbolAddress(&p, g_xl);      xl      = (float*)p;
      cudaGetSymbolAddress(&p, g_h1);      h1      = (float*)p;
      cudaGetSymbolAddress(&p, g_h2);      h2      = (float*)p;
      cudaGetSymbolAddress(&p, g_as);      as      = (float*)p;
      cudaGetSymbolAddress(&p, g_ad);      ad      = (float*)p;
      cudaGetSymbolAddress(&p, g_pool);    pool    = (float*)p;
      cudaGetSymbolAddress(&p, g_csr_src); csr_src = (int*)p;
      cudaGetSymbolAddress(&p, g_row_ptr); row_ptr = (int*)p;
      cudaGetSymbolAddress(&p, g_cnt);     cnt     = (int*)p;
      cudaGetSymbolAddress(&p, g_cursor);  cursor  = (int*)p;
    }

    // ---- CSR build (edges identical for all 3 layers) ----
    k_zero_cnt<<<(n + 255) / 256, 256>>>(cnt, n);
    k_count   <<<(Etot + 255) / 256, 256>>>(ei, E, Etot, cnt);
    k_scan    <<<1, 1024>>>(cnt, row_ptr, cursor, n);
    k_scatter <<<(Etot + 255) / 256, 256>>>(ei, E, Etot, cursor, csr_src);

    auto run_layer = [&](const float* in, int K, int H,
                         const float* W, const float* a_s, const float* a_d,
                         const float* b, float* out, int relu) {
        int M = H * HIDC;
        dim3 gg(M / BN, (n + BM - 1) / BM);
        k_gemm_tf32<<<gg, 256>>>(in, W, xl, n, K, M);
        k_attn<<<n, 32 * H>>>(xl, a_s, a_d, as, ad, H, HIDC, M);
        int warps = n * H;
        k_node_agg<<<(warps * 32 + 255) / 256, 256>>>(csr_src, row_ptr, xl, as, ad,
                                                      b, out, n, H, M, relu);
    };

    run_layer(x,  DIN,          NHEADS, W0, as0, ad0, b0, h1, 1);
    run_layer(h1, NHEADS*HIDC,  NHEADS, W1, as1, ad1, b1, h2, 1);
    run_layer(h2, NHEADS*HIDC,  1,      W2, as2, ad2, b2, h1, 0);

    k_zero_pool<<<1, HIDC>>>(pool);
    k_pool<<<256, HIDC>>>(h1, pool, n);
    k_mlp<<<1, HIDC>>>(pool, Wm1, bm1, Wm2, bm2, (float*)d_out, 1.f / (float)n);
}